// round 11
// baseline (speedup 1.0000x reference)
#include <cuda_runtime.h>
#include <cuda_bf16.h>
#include <cuda_fp16.h>
#include <math.h>
#include <stdint.h>

#define NB 8
#define LQ 2048
#define CC 256
#define MM 8
#define LL 4
#define PP 4
#define DH 32
#define S_TOTAL 3840
#define MLP 128
#define LP 16
#define KDIM 256

// ---------------- scratch (no allocs allowed) ----------------
__device__ __align__(16) __half g_value_h[NB * S_TOTAL * CC];   // [n][t][m*32+dh] fp16 (natural)
__device__ __align__(16) __nv_bfloat16 g_inp_hi[NB * S_TOTAL * CC];
__device__ __align__(16) __nv_bfloat16 g_inp_lo[NB * S_TOTAL * CC];
__device__ __align__(16) __nv_bfloat16 g_q_hi[NB * LQ * CC];
__device__ __align__(16) __nv_bfloat16 g_q_lo[NB * LQ * CC];
__device__ __align__(16) __nv_bfloat16 g_mx_hi[NB * LQ * CC];
__device__ __align__(16) __nv_bfloat16 g_mx_lo[NB * LQ * CC];
__device__ __align__(16) __nv_bfloat16 g_wv_hi[CC * KDIM], g_wv_lo[CC * KDIM];
__device__ __align__(16) __nv_bfloat16 g_wo_hi[MLP * KDIM], g_wo_lo[MLP * KDIM];
__device__ __align__(16) __nv_bfloat16 g_wa_hi[MLP * KDIM], g_wa_lo[MLP * KDIM];
__device__ __align__(16) __nv_bfloat16 g_wu_hi[CC * KDIM], g_wu_lo[CC * KDIM];

// ---------------- helpers ----------------
__device__ __forceinline__ uint32_t smem_u32(const void* p) {
    uint32_t a;
    asm("{ .reg .u64 t; cvta.to.shared.u64 t, %1; cvt.u32.u64 %0, t; }" : "=r"(a) : "l"(p));
    return a;
}
static __device__ __forceinline__ uint32_t swz128(uint32_t off) { return off ^ ((off >> 3) & 0x70); }

#define CP_ASYNC16(dst, src) \
    asm volatile("cp.async.cg.shared.global [%0], [%1], 16;" :: "r"(dst), "l"(src))
#define CP_COMMIT() asm volatile("cp.async.commit_group;" ::: "memory")
#define CP_WAIT1() asm volatile("cp.async.wait_group 1;" ::: "memory")
#define CP_WAIT0() asm volatile("cp.async.wait_group 0;" ::: "memory")

#define LDMATRIX_X4(r0, r1, r2, r3, addr) \
    asm volatile("ldmatrix.sync.aligned.m8n8.x4.shared.b16 {%0,%1,%2,%3}, [%4];" \
        : "=r"(r0), "=r"(r1), "=r"(r2), "=r"(r3) : "r"(addr))

#define MMA_BF16(c, a, b) \
    asm volatile("mma.sync.aligned.m16n8k16.row.col.f32.bf16.bf16.f32 " \
        "{%0,%1,%2,%3}, {%4,%5,%6,%7}, {%8,%9}, {%0,%1,%2,%3};" \
        : "+f"((c)[0]), "+f"((c)[1]), "+f"((c)[2]), "+f"((c)[3]) \
        : "r"((a)[0]), "r"((a)[1]), "r"((a)[2]), "r"((a)[3]), "r"((b)[0]), "r"((b)[1]))

// ---------------- weight transpose + split (W[k,n] -> Wt_hi/lo[n,k]) ----------------
__global__ void prep_weights_kernel(
    const float* __restrict__ Wv, const float* __restrict__ Wo,
    const float* __restrict__ Wa, const float* __restrict__ Wu)
{
    int i = blockIdx.x * blockDim.x + threadIdx.x;
    if (i >= 2 * CC * KDIM + 2 * MLP * KDIM) return;
    const float* W; __nv_bfloat16 *H, *Lo; int Nw, j;
    if (i < CC * KDIM)                       { W = Wv; H = g_wv_hi; Lo = g_wv_lo; Nw = CC;  j = i; }
    else if (i < CC * KDIM + MLP * KDIM)     { W = Wo; H = g_wo_hi; Lo = g_wo_lo; Nw = MLP; j = i - CC * KDIM; }
    else if (i < CC * KDIM + 2 * MLP * KDIM) { W = Wa; H = g_wa_hi; Lo = g_wa_lo; Nw = MLP; j = i - CC * KDIM - MLP * KDIM; }
    else                                     { W = Wu; H = g_wu_hi; Lo = g_wu_lo; Nw = CC;  j = i - CC * KDIM - 2 * MLP * KDIM; }
    int k = j & (KDIM - 1);
    int n = j >> 8;
    float x = W[k * Nw + n];
    __nv_bfloat16 h = __float2bfloat16(x);
    H[j] = h;
    Lo[j] = __float2bfloat16(x - __bfloat162float(h));
}

// ---------------- activation split fp32 -> hi/lo bf16 ----------------
__global__ void __launch_bounds__(256) split_kernel(
    const float* __restrict__ x, __nv_bfloat16* __restrict__ hi,
    __nv_bfloat16* __restrict__ lo, int n4)
{
    int i = blockIdx.x * blockDim.x + threadIdx.x;
    if (i >= n4) return;
    float4 v = ((const float4*)x)[i];
    float f[4] = {v.x, v.y, v.z, v.w};
    __nv_bfloat16 h[4], l[4];
#pragma unroll
    for (int t = 0; t < 4; t++) {
        h[t] = __float2bfloat16(f[t]);
        l[t] = __float2bfloat16(f[t] - __bfloat162float(h[t]));
    }
    ((__nv_bfloat162*)hi)[2 * i]     = __nv_bfloat162(h[0], h[1]);
    ((__nv_bfloat162*)hi)[2 * i + 1] = __nv_bfloat162(h[2], h[3]);
    ((__nv_bfloat162*)lo)[2 * i]     = __nv_bfloat162(l[0], l[1]);
    ((__nv_bfloat162*)lo)[2 * i + 1] = __nv_bfloat162(l[2], l[3]);
}

// ---------------- HMMA GEMM, shared-tile 3-pass: AhBh + AhBl + AlBh ----------------
// modes: 0 = bias->f32 out; 1 = loc epilogue; 2 = softmax epilogue; 3 = fp16 store (natural layout)
__global__ void __launch_bounds__(256) gemm_hmma_kernel(
    const __nv_bfloat16* __restrict__ Ahi, const __nv_bfloat16* __restrict__ Alo,
    const __nv_bfloat16* __restrict__ Bhi, const __nv_bfloat16* __restrict__ Blo,
    const float* __restrict__ bias, float* __restrict__ out,
    int Ndim, int mode, const float* __restrict__ rp)
{
    extern __shared__ char smem[];
    uint32_t sb = smem_u32(smem);
    const int tid = threadIdx.x;
    const int lane = tid & 31;
    const int wid = tid >> 5;
    const int warpm = wid & 3;
    const int warpn = wid >> 2;
    const int rowBase = blockIdx.x * 128;
    const int colBase = blockIdx.y * 128;

    const int seg = tid & 7;
    const int r0 = tid >> 3;

    float acc[2][8][4];
#pragma unroll
    for (int a = 0; a < 2; a++)
#pragma unroll
        for (int b = 0; b < 8; b++)
#pragma unroll
            for (int c = 0; c < 4; c++) acc[a][b][c] = 0.f;

#define LOAD_SLAB(c, stage) do { \
        uint32_t _base = sb + (stage) * 65536u; \
        _Pragma("unroll") \
        for (int _j = 0; _j < 4; _j++) { \
            int _row = r0 + 32 * _j; \
            uint32_t _sw = swz128(_row * 128 + seg * 16); \
            size_t _ga = (size_t)(rowBase + _row) * KDIM + (c) * 64 + seg * 8; \
            size_t _gb = (size_t)(colBase + _row) * KDIM + (c) * 64 + seg * 8; \
            CP_ASYNC16(_base + _sw,          Ahi + _ga); \
            CP_ASYNC16(_base + 16384u + _sw, Alo + _ga); \
            CP_ASYNC16(_base + 32768u + _sw, Bhi + _gb); \
            CP_ASYNC16(_base + 49152u + _sw, Blo + _gb); \
        } \
        CP_COMMIT(); \
    } while (0)

    LOAD_SLAB(0, 0);

    for (int c = 0; c < 4; c++) {
        int stage = c & 1;
        if (c < 3) { LOAD_SLAB(c + 1, stage ^ 1); CP_WAIT1(); }
        else CP_WAIT0();
        __syncthreads();

        uint32_t base = sb + stage * 65536u;
#pragma unroll
        for (int kk = 0; kk < 4; kk++) {
            uint32_t ah[2][4], al[2][4];
#pragma unroll
            for (int mt = 0; mt < 2; mt++) {
                uint32_t aoff = swz128((warpm * 32 + mt * 16 + (lane & 15)) * 128
                                       + kk * 32 + ((lane >> 4) << 4));
                LDMATRIX_X4(ah[mt][0], ah[mt][1], ah[mt][2], ah[mt][3], base + aoff);
                LDMATRIX_X4(al[mt][0], al[mt][1], al[mt][2], al[mt][3], base + 16384u + aoff);
            }
            uint32_t bh[8][2], bl[8][2];
#pragma unroll
            for (int pb = 0; pb < 4; pb++) {
                uint32_t boff = swz128((warpn * 64 + pb * 16 + ((lane >> 4) << 3) + (lane & 7)) * 128
                                       + kk * 32 + (((lane >> 3) & 1) << 4));
                uint32_t t0, t1, t2, t3;
                LDMATRIX_X4(t0, t1, t2, t3, base + 32768u + boff);
                bh[2 * pb][0] = t0; bh[2 * pb][1] = t1;
                bh[2 * pb + 1][0] = t2; bh[2 * pb + 1][1] = t3;
                LDMATRIX_X4(t0, t1, t2, t3, base + 49152u + boff);
                bl[2 * pb][0] = t0; bl[2 * pb][1] = t1;
                bl[2 * pb + 1][0] = t2; bl[2 * pb + 1][1] = t3;
            }
#pragma unroll
            for (int mt = 0; mt < 2; mt++)
#pragma unroll
                for (int nt = 0; nt < 8; nt++)
                    MMA_BF16(acc[mt][nt], ah[mt], bh[nt]);
#pragma unroll
            for (int mt = 0; mt < 2; mt++)
#pragma unroll
                for (int nt = 0; nt < 8; nt++)
                    MMA_BF16(acc[mt][nt], ah[mt], bl[nt]);
#pragma unroll
            for (int mt = 0; mt < 2; mt++)
#pragma unroll
                for (int nt = 0; nt < 8; nt++)
                    MMA_BF16(acc[mt][nt], al[mt], bh[nt]);
        }
        __syncthreads();
    }

    // ---- epilogue ----
#pragma unroll
    for (int nt = 0; nt < 8; nt++) {
        int c = colBase + warpn * 64 + nt * 8 + 2 * (lane & 3);
        float b0 = __ldg(&bias[c]);
        float b1 = __ldg(&bias[c + 1]);
#pragma unroll
        for (int mt = 0; mt < 2; mt++) {
            acc[mt][nt][0] += b0; acc[mt][nt][1] += b1;
            acc[mt][nt][2] += b0; acc[mt][nt][3] += b1;
        }
    }

    if (mode == 1) {
#pragma unroll
        for (int mt = 0; mt < 2; mt++)
#pragma unroll
            for (int h = 0; h < 2; h++) {
                int row = rowBase + warpm * 32 + mt * 16 + h * 8 + (lane >> 2);
                float4 rp4 = __ldg((const float4*)rp + row);
                float rparr[4] = {rp4.x, rp4.y, rp4.z, rp4.w};
#pragma unroll
                for (int nt = 0; nt < 8; nt++) {
                    int l = (((warpn * 64 + nt * 8 + 2 * (lane & 3))) >> 2) & 3;
                    float invlen = __uint_as_float((uint32_t)(116 + l) << 23);
                    acc[mt][nt][2 * h]     = rparr[l] + acc[mt][nt][2 * h] * invlen;
                    acc[mt][nt][2 * h + 1] = rparr[l] + acc[mt][nt][2 * h + 1] * invlen;
                }
            }
    } else if (mode == 2) {
#pragma unroll
        for (int mt = 0; mt < 2; mt++)
#pragma unroll
            for (int h = 0; h < 2; h++)
#pragma unroll
                for (int g = 0; g < 4; g++) {
                    float v0 = acc[mt][2 * g][2 * h], v1 = acc[mt][2 * g][2 * h + 1];
                    float v2 = acc[mt][2 * g + 1][2 * h], v3 = acc[mt][2 * g + 1][2 * h + 1];
                    float mx = fmaxf(fmaxf(v0, v1), fmaxf(v2, v3));
                    mx = fmaxf(mx, __shfl_xor_sync(0xffffffffu, mx, 1));
                    mx = fmaxf(mx, __shfl_xor_sync(0xffffffffu, mx, 2));
                    v0 = expf(v0 - mx); v1 = expf(v1 - mx);
                    v2 = expf(v2 - mx); v3 = expf(v3 - mx);
                    float s = v0 + v1 + v2 + v3;
                    s += __shfl_xor_sync(0xffffffffu, s, 1);
                    s += __shfl_xor_sync(0xffffffffu, s, 2);
                    float inv = 1.0f / s;
                    acc[mt][2 * g][2 * h] = v0 * inv; acc[mt][2 * g][2 * h + 1] = v1 * inv;
                    acc[mt][2 * g + 1][2 * h] = v2 * inv; acc[mt][2 * g + 1][2 * h + 1] = v3 * inv;
                }
    }

    if (mode == 3) {
        // fp16 store, natural layout: oph[row*CC + col] — same shape as float2 path, half width
        __half* oph = (__half*)out;
#pragma unroll
        for (int mt = 0; mt < 2; mt++)
#pragma unroll
            for (int h = 0; h < 2; h++) {
                int row = rowBase + warpm * 32 + mt * 16 + h * 8 + (lane >> 2);
#pragma unroll
                for (int nt = 0; nt < 8; nt++) {
                    int col = colBase + warpn * 64 + nt * 8 + 2 * (lane & 3);
                    *(__half2*)(oph + (size_t)row * CC + col) =
                        __floats2half2_rn(acc[mt][nt][2 * h], acc[mt][nt][2 * h + 1]);
                }
            }
    } else {
#pragma unroll
        for (int mt = 0; mt < 2; mt++)
#pragma unroll
            for (int h = 0; h < 2; h++) {
                int row = rowBase + warpm * 32 + mt * 16 + h * 8 + (lane >> 2);
#pragma unroll
                for (int nt = 0; nt < 8; nt++) {
                    int col = colBase + warpn * 64 + nt * 8 + 2 * (lane & 3);
                    float2 o = {acc[mt][nt][2 * h], acc[mt][nt][2 * h + 1]};
                    *(float2*)(out + (size_t)row * Ndim + col) = o;
                }
            }
    }
}

// ---------------- deform: one warp per (n,q,m); fp16 taps, lanes split tap0/tap1 ----------------
// value fp16 natural layout [n][t][m*32+dh]; per sample: lanes 0-15 read tap0's 16 half2 (64B),
// lanes 16-31 read tap1's (64B); combine via shfl_xor 16.
__global__ void __launch_bounds__(256) deform_kernel(
    const float* __restrict__ d_loc, const float* __restrict__ d_attn)
{
    int gtid = blockIdx.x * blockDim.x + threadIdx.x;
    int warp = gtid >> 5;
    int lane = gtid & 31;
    if (warp >= NB * LQ * MM) return;

    int m = warp % MM;
    int nq = warp / MM;
    int n = nq / LQ;

    float v = (lane < 16) ? d_loc[(size_t)warp * LP + lane]
                          : d_attn[(size_t)warp * LP + (lane - 16)];

    const int leni[LL] = {2048, 1024, 512, 256};
    const float lenf[LL] = {2048.f, 1024.f, 512.f, 256.f};
    const int starti[LL] = {0, 2048, 3072, 3584};

    // half2 index of (n, t=0, m, ch=0): rows are CC/2=128 half2 wide, head offset m*16
    const __half2* base2 = (const __half2*)g_value_h + (size_t)n * S_TOTAL * (CC / 2) + m * (DH / 2);
    int tap = lane >> 4;        // 0: tap0 lanes, 1: tap1 lanes
    int klo = lane & 15;        // channel pair index

    float acc0 = 0.f, acc1 = 0.f;
#pragma unroll
    for (int i = 0; i < LP; i++) {
        float loc = __shfl_sync(0xffffffffu, v, i);
        float aw = __shfl_sync(0xffffffffu, v, i + 16);
        int l = i >> 2;
        int Ti = leni[l];
        float pos = loc * lenf[l] - 0.5f;
        float x0f = floorf(pos);
        float frac = pos - x0f;
        int x0 = (int)x0f;
        float w0 = (x0 >= 0 && x0 < Ti) ? (1.0f - frac) : 0.0f;
        float w1 = (x0 + 1 >= 0 && x0 + 1 < Ti) ? frac : 0.0f;
        int t0 = min(max(x0, 0), Ti - 2);
        // distribute (w0 @ row x0, w1 @ row x0+1) onto physical rows t0, t0+1
        float wa = (t0 == x0) ? w0 : ((t0 == x0 + 1) ? w1 : 0.0f);
        float wb = (t0 + 1 == x0) ? w0 : ((t0 + 1 == x0 + 1) ? w1 : 0.0f);
        float w = tap ? wb : wa;

        __half2 hv = base2[(size_t)(starti[l] + t0 + tap) * (CC / 2) + klo];
        float2 f = __half22float2(hv);
        float p0 = w * f.x;
        float p1 = w * f.y;
        p0 += __shfl_xor_sync(0xffffffffu, p0, 16);
        p1 += __shfl_xor_sync(0xffffffffu, p1, 16);
        acc0 += aw * p0;
        acc1 += aw * p1;
    }

    if (lane < 16) {
        size_t oi = (size_t)nq * CC + m * DH + 2 * klo;
        __nv_bfloat16 h0 = __float2bfloat16(acc0);
        __nv_bfloat16 h1 = __float2bfloat16(acc1);
        *(__nv_bfloat162*)(g_mx_hi + oi) = __nv_bfloat162(h0, h1);
        *(__nv_bfloat162*)(g_mx_lo + oi) = __nv_bfloat162(
            __float2bfloat16(acc0 - __bfloat162float(h0)),
            __float2bfloat16(acc1 - __bfloat162float(h1)));
    }
}

// ---------------- launch ----------------
extern "C" void kernel_launch(void* const* d_in, const int* in_sizes, int n_in,
                              void* d_out, int out_size)
{
    const float* query  = (const float*)d_in[0];
    const float* rp     = (const float*)d_in[1];
    const float* inp    = (const float*)d_in[2];
    const float* W_off  = (const float*)d_in[5];
    const float* b_off  = (const float*)d_in[6];
    const float* W_attn = (const float*)d_in[7];
    const float* b_attn = (const float*)d_in[8];
    const float* W_val  = (const float*)d_in[9];
    const float* b_val  = (const float*)d_in[10];
    const float* W_out  = (const float*)d_in[11];
    const float* b_out  = (const float*)d_in[12];

    float* out    = (float*)d_out;
    float* o_loc  = out + (size_t)NB * LQ * CC;
    float* o_attn = o_loc + (size_t)NB * LQ * MLP;

    cudaFuncSetAttribute(gemm_hmma_kernel, cudaFuncAttributeMaxDynamicSharedMemorySize, 131072);

    __half* valueh;
    __nv_bfloat16 *ih, *il, *qh, *ql, *mh, *ml;
    __nv_bfloat16 *wvh, *wvl, *woh, *wol, *wah, *wal, *wuh, *wul;
    cudaGetSymbolAddress((void**)&valueh, g_value_h);
    cudaGetSymbolAddress((void**)&ih, g_inp_hi);  cudaGetSymbolAddress((void**)&il, g_inp_lo);
    cudaGetSymbolAddress((void**)&qh, g_q_hi);    cudaGetSymbolAddress((void**)&ql, g_q_lo);
    cudaGetSymbolAddress((void**)&mh, g_mx_hi);   cudaGetSymbolAddress((void**)&ml, g_mx_lo);
    cudaGetSymbolAddress((void**)&wvh, g_wv_hi);  cudaGetSymbolAddress((void**)&wvl, g_wv_lo);
    cudaGetSymbolAddress((void**)&woh, g_wo_hi);  cudaGetSymbolAddress((void**)&wol, g_wo_lo);
    cudaGetSymbolAddress((void**)&wah, g_wa_hi);  cudaGetSymbolAddress((void**)&wal, g_wa_lo);
    cudaGetSymbolAddress((void**)&wuh, g_wu_hi);  cudaGetSymbolAddress((void**)&wul, g_wu_lo);

    // fork/join streams (capturable fork via events)
    cudaStream_t s2;
    cudaStreamCreateWithFlags(&s2, cudaStreamNonBlocking);
    cudaEvent_t e1, e2;
    cudaEventCreateWithFlags(&e1, cudaEventDisableTiming);
    cudaEventCreateWithFlags(&e2, cudaEventDisableTiming);

    prep_weights_kernel<<<(2 * CC * KDIM + 2 * MLP * KDIM + 255) / 256, 256>>>(W_val, W_off, W_attn, W_out);
    cudaEventRecord(e1, 0);
    cudaStreamWaitEvent(s2, e1, 0);

    // side stream: q split -> loc GEMM -> attn GEMM
    split_kernel<<<(NB * LQ * CC / 4 + 255) / 256, 256, 0, s2>>>(query, qh, ql, NB * LQ * CC / 4);
    gemm_hmma_kernel<<<dim3(NB * LQ / 128, 1), 256, 131072, s2>>>(qh, ql, woh, wol, b_off, o_loc, MLP, 1, rp);
    gemm_hmma_kernel<<<dim3(NB * LQ / 128, 1), 256, 131072, s2>>>(qh, ql, wah, wal, b_attn, o_attn, MLP, 2, nullptr);
    cudaEventRecord(e2, s2);

    // main stream: inp split + value GEMM (fp16 natural-layout store)
    split_kernel<<<(NB * S_TOTAL * CC / 4 + 255) / 256, 256>>>(inp, ih, il, NB * S_TOTAL * CC / 4);
    gemm_hmma_kernel<<<dim3(NB * S_TOTAL / 128, CC / 128), 256, 131072>>>(ih, il, wvh, wvl, b_val, (float*)valueh, CC, 3, nullptr);

    // join, then deform + output projection
    cudaStreamWaitEvent(0, e2, 0);
    deform_kernel<<<(NB * LQ * MM * 32) / 256, 256>>>(o_loc, o_attn);
    gemm_hmma_kernel<<<dim3(NB * LQ / 128, CC / 128), 256, 131072>>>(mh, ml, wuh, wul, b_out, out, CC, 0, nullptr);
}

// round 12
// speedup vs baseline: 1.5078x; 1.5078x over previous
#include <cuda_runtime.h>
#include <cuda_bf16.h>
#include <cuda_fp16.h>
#include <math.h>
#include <stdint.h>

#define NB 8
#define LQ 2048
#define CC 256
#define MM 8
#define LL 4
#define PP 4
#define DH 32
#define S_TOTAL 3840
#define MLP 128
#define LP 16
#define KDIM 256

// ---------------- scratch (no allocs allowed) ----------------
__device__ __align__(16) __half g_value_h[NB * S_TOTAL * CC];   // [n][t][m*32+dh] fp16
__device__ __align__(16) __nv_bfloat16 g_inp_hi[NB * S_TOTAL * CC];
__device__ __align__(16) __nv_bfloat16 g_inp_lo[NB * S_TOTAL * CC];
__device__ __align__(16) __nv_bfloat16 g_q_hi[NB * LQ * CC];
__device__ __align__(16) __nv_bfloat16 g_q_lo[NB * LQ * CC];
__device__ __align__(16) __nv_bfloat16 g_mx_hi[NB * LQ * CC];
__device__ __align__(16) __nv_bfloat16 g_mx_lo[NB * LQ * CC];
__device__ __align__(16) __nv_bfloat16 g_wv_hi[CC * KDIM], g_wv_lo[CC * KDIM];
__device__ __align__(16) __nv_bfloat16 g_wo_hi[MLP * KDIM], g_wo_lo[MLP * KDIM];
__device__ __align__(16) __nv_bfloat16 g_wa_hi[MLP * KDIM], g_wa_lo[MLP * KDIM];
__device__ __align__(16) __nv_bfloat16 g_wu_hi[CC * KDIM], g_wu_lo[CC * KDIM];

// ---------------- helpers ----------------
__device__ __forceinline__ uint32_t smem_u32(const void* p) {
    uint32_t a;
    asm("{ .reg .u64 t; cvta.to.shared.u64 t, %1; cvt.u32.u64 %0, t; }" : "=r"(a) : "l"(p));
    return a;
}
static __device__ __forceinline__ uint32_t swz128(uint32_t off) { return off ^ ((off >> 3) & 0x70); }

#define CP_ASYNC16(dst, src) \
    asm volatile("cp.async.cg.shared.global [%0], [%1], 16;" :: "r"(dst), "l"(src))
#define CP_COMMIT() asm volatile("cp.async.commit_group;" ::: "memory")
#define CP_WAIT1() asm volatile("cp.async.wait_group 1;" ::: "memory")
#define CP_WAIT0() asm volatile("cp.async.wait_group 0;" ::: "memory")

#define LDMATRIX_X4(r0, r1, r2, r3, addr) \
    asm volatile("ldmatrix.sync.aligned.m8n8.x4.shared.b16 {%0,%1,%2,%3}, [%4];" \
        : "=r"(r0), "=r"(r1), "=r"(r2), "=r"(r3) : "r"(addr))

#define MMA_BF16(c, a, b) \
    asm volatile("mma.sync.aligned.m16n8k16.row.col.f32.bf16.bf16.f32 " \
        "{%0,%1,%2,%3}, {%4,%5,%6,%7}, {%8,%9}, {%0,%1,%2,%3};" \
        : "+f"((c)[0]), "+f"((c)[1]), "+f"((c)[2]), "+f"((c)[3]) \
        : "r"((a)[0]), "r"((a)[1]), "r"((a)[2]), "r"((a)[3]), "r"((b)[0]), "r"((b)[1]))

// ---------------- weight transpose + split (W[k,n] -> Wt_hi/lo[n,k]) ----------------
__global__ void prep_weights_kernel(
    const float* __restrict__ Wv, const float* __restrict__ Wo,
    const float* __restrict__ Wa, const float* __restrict__ Wu)
{
    int i = blockIdx.x * blockDim.x + threadIdx.x;
    if (i >= 2 * CC * KDIM + 2 * MLP * KDIM) return;
    const float* W; __nv_bfloat16 *H, *Lo; int Nw, j;
    if (i < CC * KDIM)                       { W = Wv; H = g_wv_hi; Lo = g_wv_lo; Nw = CC;  j = i; }
    else if (i < CC * KDIM + MLP * KDIM)     { W = Wo; H = g_wo_hi; Lo = g_wo_lo; Nw = MLP; j = i - CC * KDIM; }
    else if (i < CC * KDIM + 2 * MLP * KDIM) { W = Wa; H = g_wa_hi; Lo = g_wa_lo; Nw = MLP; j = i - CC * KDIM - MLP * KDIM; }
    else                                     { W = Wu; H = g_wu_hi; Lo = g_wu_lo; Nw = CC;  j = i - CC * KDIM - 2 * MLP * KDIM; }
    int k = j & (KDIM - 1);
    int n = j >> 8;
    float x = W[k * Nw + n];
    __nv_bfloat16 h = __float2bfloat16(x);
    H[j] = h;
    Lo[j] = __float2bfloat16(x - __bfloat162float(h));
}

// ---------------- fused activation split: inp then query ----------------
__global__ void __launch_bounds__(256) split2_kernel(
    const float* __restrict__ xa, __nv_bfloat16* __restrict__ hia, __nv_bfloat16* __restrict__ loa, int n4a,
    const float* __restrict__ xb, __nv_bfloat16* __restrict__ hib, __nv_bfloat16* __restrict__ lob, int n4b)
{
    int i = blockIdx.x * blockDim.x + threadIdx.x;
    const float* x; __nv_bfloat16 *hi, *lo;
    if (i < n4a) { x = xa; hi = hia; lo = loa; }
    else {
        i -= n4a;
        if (i >= n4b) return;
        x = xb; hi = hib; lo = lob;
    }
    float4 v = ((const float4*)x)[i];
    float f[4] = {v.x, v.y, v.z, v.w};
    __nv_bfloat16 h[4], l[4];
#pragma unroll
    for (int t = 0; t < 4; t++) {
        h[t] = __float2bfloat16(f[t]);
        l[t] = __float2bfloat16(f[t] - __bfloat162float(h[t]));
    }
    ((__nv_bfloat162*)hi)[2 * i]     = __nv_bfloat162(h[0], h[1]);
    ((__nv_bfloat162*)hi)[2 * i + 1] = __nv_bfloat162(h[2], h[3]);
    ((__nv_bfloat162*)lo)[2 * i]     = __nv_bfloat162(l[0], l[1]);
    ((__nv_bfloat162*)lo)[2 * i + 1] = __nv_bfloat162(l[2], l[3]);
}

// ---------------- HMMA GEMM, shared-tile 3-pass: AhBh + AhBl + AlBh ----------------
// modes: 0 = bias->f32; 1 = loc; 2 = softmax; 3 = fp16 store; 4 = paired side (y0: loc, y1: attn via B2/bias2/out2)
__global__ void __launch_bounds__(256) gemm_hmma_kernel(
    const __nv_bfloat16* __restrict__ Ahi, const __nv_bfloat16* __restrict__ Alo,
    const __nv_bfloat16* __restrict__ Bhi, const __nv_bfloat16* __restrict__ Blo,
    const float* __restrict__ bias, float* __restrict__ out,
    int Ndim, int mode, const float* __restrict__ rp,
    const __nv_bfloat16* __restrict__ B2h, const __nv_bfloat16* __restrict__ B2l,
    const float* __restrict__ bias2, float* __restrict__ out2)
{
    extern __shared__ char smem[];
    uint32_t sb = smem_u32(smem);
    const int tid = threadIdx.x;
    const int lane = tid & 31;
    const int wid = tid >> 5;
    const int warpm = wid & 3;
    const int warpn = wid >> 2;
    const int rowBase = blockIdx.x * 128;
    int colBase = blockIdx.y * 128;

    const __nv_bfloat16 *Bh_p = Bhi, *Bl_p = Blo;
    const float* bias_p = bias;
    float* out_p = out;
    int effmode = mode;
    if (mode == 4) {
        colBase = 0;
        if (blockIdx.y == 0) { effmode = 1; }
        else { effmode = 2; Bh_p = B2h; Bl_p = B2l; bias_p = bias2; out_p = out2; }
    }

    const int seg = tid & 7;
    const int r0 = tid >> 3;

    float acc[2][8][4];
#pragma unroll
    for (int a = 0; a < 2; a++)
#pragma unroll
        for (int b = 0; b < 8; b++)
#pragma unroll
            for (int c = 0; c < 4; c++) acc[a][b][c] = 0.f;

#define LOAD_SLAB(c, stage) do { \
        uint32_t _base = sb + (stage) * 65536u; \
        _Pragma("unroll") \
        for (int _j = 0; _j < 4; _j++) { \
            int _row = r0 + 32 * _j; \
            uint32_t _sw = swz128(_row * 128 + seg * 16); \
            size_t _ga = (size_t)(rowBase + _row) * KDIM + (c) * 64 + seg * 8; \
            size_t _gb = (size_t)(colBase + _row) * KDIM + (c) * 64 + seg * 8; \
            CP_ASYNC16(_base + _sw,          Ahi  + _ga); \
            CP_ASYNC16(_base + 16384u + _sw, Alo  + _ga); \
            CP_ASYNC16(_base + 32768u + _sw, Bh_p + _gb); \
            CP_ASYNC16(_base + 49152u + _sw, Bl_p + _gb); \
        } \
        CP_COMMIT(); \
    } while (0)

    LOAD_SLAB(0, 0);

    for (int c = 0; c < 4; c++) {
        int stage = c & 1;
        if (c < 3) { LOAD_SLAB(c + 1, stage ^ 1); CP_WAIT1(); }
        else CP_WAIT0();
        __syncthreads();

        uint32_t base = sb + stage * 65536u;
#pragma unroll
        for (int kk = 0; kk < 4; kk++) {
            uint32_t ah[2][4], al[2][4];
#pragma unroll
            for (int mt = 0; mt < 2; mt++) {
                uint32_t aoff = swz128((warpm * 32 + mt * 16 + (lane & 15)) * 128
                                       + kk * 32 + ((lane >> 4) << 4));
                LDMATRIX_X4(ah[mt][0], ah[mt][1], ah[mt][2], ah[mt][3], base + aoff);
                LDMATRIX_X4(al[mt][0], al[mt][1], al[mt][2], al[mt][3], base + 16384u + aoff);
            }
            uint32_t bh[8][2], bl[8][2];
#pragma unroll
            for (int pb = 0; pb < 4; pb++) {
                uint32_t boff = swz128((warpn * 64 + pb * 16 + ((lane >> 4) << 3) + (lane & 7)) * 128
                                       + kk * 32 + (((lane >> 3) & 1) << 4));
                uint32_t t0, t1, t2, t3;
                LDMATRIX_X4(t0, t1, t2, t3, base + 32768u + boff);
                bh[2 * pb][0] = t0; bh[2 * pb][1] = t1;
                bh[2 * pb + 1][0] = t2; bh[2 * pb + 1][1] = t3;
                LDMATRIX_X4(t0, t1, t2, t3, base + 49152u + boff);
                bl[2 * pb][0] = t0; bl[2 * pb][1] = t1;
                bl[2 * pb + 1][0] = t2; bl[2 * pb + 1][1] = t3;
            }
#pragma unroll
            for (int mt = 0; mt < 2; mt++)
#pragma unroll
                for (int nt = 0; nt < 8; nt++)
                    MMA_BF16(acc[mt][nt], ah[mt], bh[nt]);
#pragma unroll
            for (int mt = 0; mt < 2; mt++)
#pragma unroll
                for (int nt = 0; nt < 8; nt++)
                    MMA_BF16(acc[mt][nt], ah[mt], bl[nt]);
#pragma unroll
            for (int mt = 0; mt < 2; mt++)
#pragma unroll
                for (int nt = 0; nt < 8; nt++)
                    MMA_BF16(acc[mt][nt], al[mt], bh[nt]);
        }
        __syncthreads();
    }

    // ---- epilogue ----
#pragma unroll
    for (int nt = 0; nt < 8; nt++) {
        int c = colBase + warpn * 64 + nt * 8 + 2 * (lane & 3);
        float b0 = __ldg(&bias_p[c]);
        float b1 = __ldg(&bias_p[c + 1]);
#pragma unroll
        for (int mt = 0; mt < 2; mt++) {
            acc[mt][nt][0] += b0; acc[mt][nt][1] += b1;
            acc[mt][nt][2] += b0; acc[mt][nt][3] += b1;
        }
    }

    if (effmode == 1) {
#pragma unroll
        for (int mt = 0; mt < 2; mt++)
#pragma unroll
            for (int h = 0; h < 2; h++) {
                int row = rowBase + warpm * 32 + mt * 16 + h * 8 + (lane >> 2);
                float4 rp4 = __ldg((const float4*)rp + row);
                float rparr[4] = {rp4.x, rp4.y, rp4.z, rp4.w};
#pragma unroll
                for (int nt = 0; nt < 8; nt++) {
                    int l = (((colBase + warpn * 64 + nt * 8 + 2 * (lane & 3))) >> 2) & 3;
                    float invlen = __uint_as_float((uint32_t)(116 + l) << 23);
                    acc[mt][nt][2 * h]     = rparr[l] + acc[mt][nt][2 * h] * invlen;
                    acc[mt][nt][2 * h + 1] = rparr[l] + acc[mt][nt][2 * h + 1] * invlen;
                }
            }
    } else if (effmode == 2) {
#pragma unroll
        for (int mt = 0; mt < 2; mt++)
#pragma unroll
            for (int h = 0; h < 2; h++)
#pragma unroll
                for (int g = 0; g < 4; g++) {
                    float v0 = acc[mt][2 * g][2 * h], v1 = acc[mt][2 * g][2 * h + 1];
                    float v2 = acc[mt][2 * g + 1][2 * h], v3 = acc[mt][2 * g + 1][2 * h + 1];
                    float mx = fmaxf(fmaxf(v0, v1), fmaxf(v2, v3));
                    mx = fmaxf(mx, __shfl_xor_sync(0xffffffffu, mx, 1));
                    mx = fmaxf(mx, __shfl_xor_sync(0xffffffffu, mx, 2));
                    v0 = expf(v0 - mx); v1 = expf(v1 - mx);
                    v2 = expf(v2 - mx); v3 = expf(v3 - mx);
                    float s = v0 + v1 + v2 + v3;
                    s += __shfl_xor_sync(0xffffffffu, s, 1);
                    s += __shfl_xor_sync(0xffffffffu, s, 2);
                    float inv = 1.0f / s;
                    acc[mt][2 * g][2 * h] = v0 * inv; acc[mt][2 * g][2 * h + 1] = v1 * inv;
                    acc[mt][2 * g + 1][2 * h] = v2 * inv; acc[mt][2 * g + 1][2 * h + 1] = v3 * inv;
                }
    }

    if (effmode == 3) {
        __half* oph = (__half*)out_p;
#pragma unroll
        for (int mt = 0; mt < 2; mt++)
#pragma unroll
            for (int h = 0; h < 2; h++) {
                int row = rowBase + warpm * 32 + mt * 16 + h * 8 + (lane >> 2);
#pragma unroll
                for (int nt = 0; nt < 8; nt++) {
                    int col = colBase + warpn * 64 + nt * 8 + 2 * (lane & 3);
                    *(__half2*)(oph + (size_t)row * CC + col) =
                        __floats2half2_rn(acc[mt][nt][2 * h], acc[mt][nt][2 * h + 1]);
                }
            }
    } else {
#pragma unroll
        for (int mt = 0; mt < 2; mt++)
#pragma unroll
            for (int h = 0; h < 2; h++) {
                int row = rowBase + warpm * 32 + mt * 16 + h * 8 + (lane >> 2);
#pragma unroll
                for (int nt = 0; nt < 8; nt++) {
                    int col = colBase + warpn * 64 + nt * 8 + 2 * (lane & 3);
                    float2 o = {acc[mt][nt][2 * h], acc[mt][nt][2 * h + 1]};
                    *(float2*)(out_p + (size_t)row * Ndim + col) = o;
                }
            }
    }
}

// ---------------- deform: one warp per (n,q,m); fp16 taps, lanes split tap0/tap1 ----------------
__global__ void __launch_bounds__(256) deform_kernel(
    const float* __restrict__ d_loc, const float* __restrict__ d_attn)
{
    int gtid = blockIdx.x * blockDim.x + threadIdx.x;
    int warp = gtid >> 5;
    int lane = gtid & 31;
    if (warp >= NB * LQ * MM) return;

    int m = warp % MM;
    int nq = warp / MM;
    int n = nq / LQ;

    float v = (lane < 16) ? d_loc[(size_t)warp * LP + lane]
                          : d_attn[(size_t)warp * LP + (lane - 16)];

    const int leni[LL] = {2048, 1024, 512, 256};
    const float lenf[LL] = {2048.f, 1024.f, 512.f, 256.f};
    const int starti[LL] = {0, 2048, 3072, 3584};

    const __half2* base2 = (const __half2*)g_value_h + (size_t)n * S_TOTAL * (CC / 2) + m * (DH / 2);
    int tap = lane >> 4;
    int klo = lane & 15;

    float acc0 = 0.f, acc1 = 0.f;
#pragma unroll
    for (int i = 0; i < LP; i++) {
        float loc = __shfl_sync(0xffffffffu, v, i);
        float aw = __shfl_sync(0xffffffffu, v, i + 16);
        int l = i >> 2;
        int Ti = leni[l];
        float pos = loc * lenf[l] - 0.5f;
        float x0f = floorf(pos);
        float frac = pos - x0f;
        int x0 = (int)x0f;
        float w0 = (x0 >= 0 && x0 < Ti) ? (1.0f - frac) : 0.0f;
        float w1 = (x0 + 1 >= 0 && x0 + 1 < Ti) ? frac : 0.0f;
        int t0 = min(max(x0, 0), Ti - 2);
        float wa = (t0 == x0) ? w0 : ((t0 == x0 + 1) ? w1 : 0.0f);
        float wb = (t0 + 1 == x0) ? w0 : ((t0 + 1 == x0 + 1) ? w1 : 0.0f);
        float w = tap ? wb : wa;

        __half2 hv = base2[(size_t)(starti[l] + t0 + tap) * (CC / 2) + klo];
        float2 f = __half22float2(hv);
        float p0 = w * f.x;
        float p1 = w * f.y;
        p0 += __shfl_xor_sync(0xffffffffu, p0, 16);
        p1 += __shfl_xor_sync(0xffffffffu, p1, 16);
        acc0 += aw * p0;
        acc1 += aw * p1;
    }

    if (lane < 16) {
        size_t oi = (size_t)nq * CC + m * DH + 2 * klo;
        __nv_bfloat16 h0 = __float2bfloat16(acc0);
        __nv_bfloat16 h1 = __float2bfloat16(acc1);
        *(__nv_bfloat162*)(g_mx_hi + oi) = __nv_bfloat162(h0, h1);
        *(__nv_bfloat162*)(g_mx_lo + oi) = __nv_bfloat162(
            __float2bfloat16(acc0 - __bfloat162float(h0)),
            __float2bfloat16(acc1 - __bfloat162float(h1)));
    }
}

// ---------------- launch ----------------
extern "C" void kernel_launch(void* const* d_in, const int* in_sizes, int n_in,
                              void* d_out, int out_size)
{
    const float* query  = (const float*)d_in[0];
    const float* rp     = (const float*)d_in[1];
    const float* inp    = (const float*)d_in[2];
    const float* W_off  = (const float*)d_in[5];
    const float* b_off  = (const float*)d_in[6];
    const float* W_attn = (const float*)d_in[7];
    const float* b_attn = (const float*)d_in[8];
    const float* W_val  = (const float*)d_in[9];
    const float* b_val  = (const float*)d_in[10];
    const float* W_out  = (const float*)d_in[11];
    const float* b_out  = (const float*)d_in[12];

    float* out    = (float*)d_out;
    float* o_loc  = out + (size_t)NB * LQ * CC;
    float* o_attn = o_loc + (size_t)NB * LQ * MLP;

    cudaFuncSetAttribute(gemm_hmma_kernel, cudaFuncAttributeMaxDynamicSharedMemorySize, 131072);

    __half* valueh;
    __nv_bfloat16 *ih, *il, *qh, *ql, *mh, *ml;
    __nv_bfloat16 *wvh, *wvl, *woh, *wol, *wah, *wal, *wuh, *wul;
    cudaGetSymbolAddress((void**)&valueh, g_value_h);
    cudaGetSymbolAddress((void**)&ih, g_inp_hi);  cudaGetSymbolAddress((void**)&il, g_inp_lo);
    cudaGetSymbolAddress((void**)&qh, g_q_hi);    cudaGetSymbolAddress((void**)&ql, g_q_lo);
    cudaGetSymbolAddress((void**)&mh, g_mx_hi);   cudaGetSymbolAddress((void**)&ml, g_mx_lo);
    cudaGetSymbolAddress((void**)&wvh, g_wv_hi);  cudaGetSymbolAddress((void**)&wvl, g_wv_lo);
    cudaGetSymbolAddress((void**)&woh, g_wo_hi);  cudaGetSymbolAddress((void**)&wol, g_wo_lo);
    cudaGetSymbolAddress((void**)&wah, g_wa_hi);  cudaGetSymbolAddress((void**)&wal, g_wa_lo);
    cudaGetSymbolAddress((void**)&wuh, g_wu_hi);  cudaGetSymbolAddress((void**)&wul, g_wu_lo);

    // fork/join streams (capturable fork via events)
    cudaStream_t s2;
    cudaStreamCreateWithFlags(&s2, cudaStreamNonBlocking);
    cudaEvent_t e1, e2;
    cudaEventCreateWithFlags(&e1, cudaEventDisableTiming);
    cudaEventCreateWithFlags(&e2, cudaEventDisableTiming);

    prep_weights_kernel<<<(2 * CC * KDIM + 2 * MLP * KDIM + 255) / 256, 256>>>(W_val, W_off, W_attn, W_out);
    // fused split: inp + query
    split2_kernel<<<((NB * S_TOTAL * CC + NB * LQ * CC) / 4 + 255) / 256, 256>>>(
        inp, ih, il, NB * S_TOTAL * CC / 4, query, qh, ql, NB * LQ * CC / 4);
    cudaEventRecord(e1, 0);
    cudaStreamWaitEvent(s2, e1, 0);

    // side stream: merged loc+attn GEMM (grid.y: 0=loc, 1=attn)
    gemm_hmma_kernel<<<dim3(NB * LQ / 128, 2), 256, 131072, s2>>>(
        qh, ql, woh, wol, b_off, o_loc, MLP, 4, rp, wah, wal, b_attn, o_attn);
    cudaEventRecord(e2, s2);

    // main stream: value GEMM (fp16 natural-layout store)
    gemm_hmma_kernel<<<dim3(NB * S_TOTAL / 128, CC / 128), 256, 131072>>>(
        ih, il, wvh, wvl, b_val, (float*)valueh, CC, 3, nullptr, nullptr, nullptr, nullptr, nullptr);

    // join, then deform + output projection
    cudaStreamWaitEvent(0, e2, 0);
    deform_kernel<<<(NB * LQ * MM * 32) / 256, 256>>>(o_loc, o_attn);
    gemm_hmma_kernel<<<dim3(NB * LQ / 128, CC / 128), 256, 131072>>>(
        mh, ml, wuh, wul, b_out, out, CC, 0, nullptr, nullptr, nullptr, nullptr, nullptr);
}

// round 14
// speedup vs baseline: 1.5398x; 1.0212x over previous
#include <cuda_runtime.h>
#include <cuda_bf16.h>
#include <cuda_fp16.h>
#include <math.h>
#include <stdint.h>

#define NB 8
#define LQ 2048
#define CC 256
#define MM 8
#define LL 4
#define PP 4
#define DH 32
#define S_TOTAL 3840
#define MLP 128
#define LP 16
#define KDIM 256

// ---------------- scratch (no allocs allowed) ----------------
__device__ __align__(16) __half g_value_h[NB * S_TOTAL * CC];   // [n][t][m*32+dh] fp16
__device__ __align__(16) __nv_bfloat16 g_inp_hi[NB * S_TOTAL * CC];
__device__ __align__(16) __nv_bfloat16 g_inp_lo[NB * S_TOTAL * CC];
__device__ __align__(16) __nv_bfloat16 g_q_hi[NB * LQ * CC];
__device__ __align__(16) __nv_bfloat16 g_q_lo[NB * LQ * CC];
__device__ __align__(16) __nv_bfloat16 g_mx_hi[NB * LQ * CC];
__device__ __align__(16) __nv_bfloat16 g_mx_lo[NB * LQ * CC];
__device__ __align__(16) __nv_bfloat16 g_wv_hi[CC * KDIM], g_wv_lo[CC * KDIM];
__device__ __align__(16) __nv_bfloat16 g_wo_hi[MLP * KDIM], g_wo_lo[MLP * KDIM];
__device__ __align__(16) __nv_bfloat16 g_wa_hi[MLP * KDIM], g_wa_lo[MLP * KDIM];
__device__ __align__(16) __nv_bfloat16 g_wu_hi[CC * KDIM], g_wu_lo[CC * KDIM];

// ---------------- helpers ----------------
__device__ __forceinline__ uint32_t smem_u32(const void* p) {
    uint32_t a;
    asm("{ .reg .u64 t; cvta.to.shared.u64 t, %1; cvt.u32.u64 %0, t; }" : "=r"(a) : "l"(p));
    return a;
}
static __device__ __forceinline__ uint32_t swz64(uint32_t off) { return off ^ ((off >> 3) & 0x30); }

#define CP_ASYNC16(dst, src) \
    asm volatile("cp.async.cg.shared.global [%0], [%1], 16;" :: "r"(dst), "l"(src))
#define CP_COMMIT() asm volatile("cp.async.commit_group;" ::: "memory")
#define CP_WAIT1() asm volatile("cp.async.wait_group 1;" ::: "memory")
#define CP_WAIT0() asm volatile("cp.async.wait_group 0;" ::: "memory")

#define LDMATRIX_X4(r0, r1, r2, r3, addr) \
    asm volatile("ldmatrix.sync.aligned.m8n8.x4.shared.b16 {%0,%1,%2,%3}, [%4];" \
        : "=r"(r0), "=r"(r1), "=r"(r2), "=r"(r3) : "r"(addr))

#define MMA_BF16_2(c, a, b0v, b1v) \
    asm volatile("mma.sync.aligned.m16n8k16.row.col.f32.bf16.bf16.f32 " \
        "{%0,%1,%2,%3}, {%4,%5,%6,%7}, {%8,%9}, {%0,%1,%2,%3};" \
        : "+f"((c)[0]), "+f"((c)[1]), "+f"((c)[2]), "+f"((c)[3]) \
        : "r"((a)[0]), "r"((a)[1]), "r"((a)[2]), "r"((a)[3]), "r"(b0v), "r"(b1v))

// ---------------- weight transpose + split (W[k,n] -> Wt_hi/lo[n,k]) ----------------
__global__ void prep_weights_kernel(
    const float* __restrict__ Wv, const float* __restrict__ Wo,
    const float* __restrict__ Wa, const float* __restrict__ Wu)
{
    int i = blockIdx.x * blockDim.x + threadIdx.x;
    if (i >= 2 * CC * KDIM + 2 * MLP * KDIM) return;
    const float* W; __nv_bfloat16 *H, *Lo; int Nw, j;
    if (i < CC * KDIM)                       { W = Wv; H = g_wv_hi; Lo = g_wv_lo; Nw = CC;  j = i; }
    else if (i < CC * KDIM + MLP * KDIM)     { W = Wo; H = g_wo_hi; Lo = g_wo_lo; Nw = MLP; j = i - CC * KDIM; }
    else if (i < CC * KDIM + 2 * MLP * KDIM) { W = Wa; H = g_wa_hi; Lo = g_wa_lo; Nw = MLP; j = i - CC * KDIM - MLP * KDIM; }
    else                                     { W = Wu; H = g_wu_hi; Lo = g_wu_lo; Nw = CC;  j = i - CC * KDIM - 2 * MLP * KDIM; }
    int k = j & (KDIM - 1);
    int n = j >> 8;
    float x = W[k * Nw + n];
    __nv_bfloat16 h = __float2bfloat16(x);
    H[j] = h;
    Lo[j] = __float2bfloat16(x - __bfloat162float(h));
}

// ---------------- fused activation split: inp then query ----------------
__global__ void __launch_bounds__(256) split2_kernel(
    const float* __restrict__ xa, __nv_bfloat16* __restrict__ hia, __nv_bfloat16* __restrict__ loa, int n4a,
    const float* __restrict__ xb, __nv_bfloat16* __restrict__ hib, __nv_bfloat16* __restrict__ lob, int n4b)
{
    int i = blockIdx.x * blockDim.x + threadIdx.x;
    const float* x; __nv_bfloat16 *hi, *lo;
    if (i < n4a) { x = xa; hi = hia; lo = loa; }
    else {
        i -= n4a;
        if (i >= n4b) return;
        x = xb; hi = hib; lo = lob;
    }
    float4 v = ((const float4*)x)[i];
    float f[4] = {v.x, v.y, v.z, v.w};
    __nv_bfloat16 h[4], l[4];
#pragma unroll
    for (int t = 0; t < 4; t++) {
        h[t] = __float2bfloat16(f[t]);
        l[t] = __float2bfloat16(f[t] - __bfloat162float(h[t]));
    }
    ((__nv_bfloat162*)hi)[2 * i]     = __nv_bfloat162(h[0], h[1]);
    ((__nv_bfloat162*)hi)[2 * i + 1] = __nv_bfloat162(h[2], h[3]);
    ((__nv_bfloat162*)lo)[2 * i]     = __nv_bfloat162(l[0], l[1]);
    ((__nv_bfloat162*)lo)[2 * i + 1] = __nv_bfloat162(l[2], l[3]);
}

// ---------------- HMMA GEMM, shared-tile 3-pass, BK=32, 2 CTA/SM ----------------
// stage (32KB): Ah @0, Al @8K, Bh @16K, Bl @24K; rows 64B wide, SW64 swizzle.
// modes: 0 = bias->f32; 1 = loc; 2 = softmax; 3 = fp16 store; 4 = paired side (y0: loc, y1: attn)
__global__ void __launch_bounds__(256, 2) gemm_hmma_kernel(
    const __nv_bfloat16* __restrict__ Ahi, const __nv_bfloat16* __restrict__ Alo,
    const __nv_bfloat16* __restrict__ Bhi, const __nv_bfloat16* __restrict__ Blo,
    const float* __restrict__ bias, float* __restrict__ out,
    int Ndim, int mode, const float* __restrict__ rp,
    const __nv_bfloat16* __restrict__ B2h, const __nv_bfloat16* __restrict__ B2l,
    const float* __restrict__ bias2, float* __restrict__ out2)
{
    extern __shared__ char smem[];
    uint32_t sb = smem_u32(smem);
    const int tid = threadIdx.x;
    const int lane = tid & 31;
    const int wid = tid >> 5;
    const int warpm = wid & 3;
    const int warpn = wid >> 2;
    const int rowBase = blockIdx.x * 128;
    int colBase = blockIdx.y * 128;

    const __nv_bfloat16 *Bh_p = Bhi, *Bl_p = Blo;
    const float* bias_p = bias;
    float* out_p = out;
    int effmode = mode;
    if (mode == 4) {
        colBase = 0;
        if (blockIdx.y == 0) { effmode = 1; }
        else { effmode = 2; Bh_p = B2h; Bl_p = B2l; bias_p = bias2; out_p = out2; }
    }

    const int seg = tid & 3;       // 16B seg within 64B row
    const int r0 = tid >> 2;       // 0..63

    float acc[2][8][4];
#pragma unroll
    for (int a = 0; a < 2; a++)
#pragma unroll
        for (int b = 0; b < 8; b++)
#pragma unroll
            for (int c = 0; c < 4; c++) acc[a][b][c] = 0.f;

    // BK=32: per slab c (0..7), k-offset = c*32 elements
#define LOAD_SLAB(c, stage) do { \
        uint32_t _base = sb + (stage) * 32768u; \
        _Pragma("unroll") \
        for (int _j = 0; _j < 2; _j++) { \
            int _row = r0 + 64 * _j; \
            uint32_t _sw = swz64(_row * 64 + seg * 16); \
            size_t _ga = (size_t)(rowBase + _row) * KDIM + (c) * 32 + seg * 8; \
            size_t _gb = (size_t)(colBase + _row) * KDIM + (c) * 32 + seg * 8; \
            CP_ASYNC16(_base + _sw,          Ahi  + _ga); \
            CP_ASYNC16(_base + 8192u  + _sw, Alo  + _ga); \
            CP_ASYNC16(_base + 16384u + _sw, Bh_p + _gb); \
            CP_ASYNC16(_base + 24576u + _sw, Bl_p + _gb); \
        } \
        CP_COMMIT(); \
    } while (0)

    LOAD_SLAB(0, 0);

    for (int c = 0; c < 8; c++) {
        int stage = c & 1;
        if (c < 7) { LOAD_SLAB(c + 1, stage ^ 1); CP_WAIT1(); }
        else CP_WAIT0();
        __syncthreads();

        uint32_t base = sb + stage * 32768u;
#pragma unroll
        for (int kk = 0; kk < 2; kk++) {
            uint32_t ah[2][4], al[2][4];
#pragma unroll
            for (int mt = 0; mt < 2; mt++) {
                uint32_t aoff = swz64((warpm * 32 + mt * 16 + (lane & 15)) * 64
                                      + kk * 32 + ((lane >> 4) << 4));
                LDMATRIX_X4(ah[mt][0], ah[mt][1], ah[mt][2], ah[mt][3], base + aoff);
                LDMATRIX_X4(al[mt][0], al[mt][1], al[mt][2], al[mt][3], base + 8192u + aoff);
            }
#pragma unroll
            for (int pb = 0; pb < 4; pb++) {
                uint32_t boff = swz64((warpn * 64 + pb * 16 + ((lane >> 4) << 3) + (lane & 7)) * 64
                                      + kk * 32 + (((lane >> 3) & 1) << 4));
                uint32_t h0, h1, h2, h3, l0, l1, l2, l3;
                LDMATRIX_X4(h0, h1, h2, h3, base + 16384u + boff);
                LDMATRIX_X4(l0, l1, l2, l3, base + 24576u + boff);
#pragma unroll
                for (int mt = 0; mt < 2; mt++) {
                    MMA_BF16_2(acc[mt][2 * pb],     ah[mt], h0, h1);
                    MMA_BF16_2(acc[mt][2 * pb + 1], ah[mt], h2, h3);
                    MMA_BF16_2(acc[mt][2 * pb],     ah[mt], l0, l1);
                    MMA_BF16_2(acc[mt][2 * pb + 1], ah[mt], l2, l3);
                    MMA_BF16_2(acc[mt][2 * pb],     al[mt], h0, h1);
                    MMA_BF16_2(acc[mt][2 * pb + 1], al[mt], h2, h3);
                }
            }
        }
        __syncthreads();
    }

    // ---- epilogue ----
#pragma unroll
    for (int nt = 0; nt < 8; nt++) {
        int c = colBase + warpn * 64 + nt * 8 + 2 * (lane & 3);
        float b0 = __ldg(&bias_p[c]);
        float b1 = __ldg(&bias_p[c + 1]);
#pragma unroll
        for (int mt = 0; mt < 2; mt++) {
            acc[mt][nt][0] += b0; acc[mt][nt][1] += b1;
            acc[mt][nt][2] += b0; acc[mt][nt][3] += b1;
        }
    }

    if (effmode == 1) {
#pragma unroll
        for (int mt = 0; mt < 2; mt++)
#pragma unroll
            for (int h = 0; h < 2; h++) {
                int row = rowBase + warpm * 32 + mt * 16 + h * 8 + (lane >> 2);
                float4 rp4 = __ldg((const float4*)rp + row);
                float rparr[4] = {rp4.x, rp4.y, rp4.z, rp4.w};
#pragma unroll
                for (int nt = 0; nt < 8; nt++) {
                    int l = (((colBase + warpn * 64 + nt * 8 + 2 * (lane & 3))) >> 2) & 3;
                    float invlen = __uint_as_float((uint32_t)(116 + l) << 23);
                    acc[mt][nt][2 * h]     = rparr[l] + acc[mt][nt][2 * h] * invlen;
                    acc[mt][nt][2 * h + 1] = rparr[l] + acc[mt][nt][2 * h + 1] * invlen;
                }
            }
    } else if (effmode == 2) {
#pragma unroll
        for (int mt = 0; mt < 2; mt++)
#pragma unroll
            for (int h = 0; h < 2; h++)
#pragma unroll
                for (int g = 0; g < 4; g++) {
                    float v0 = acc[mt][2 * g][2 * h], v1 = acc[mt][2 * g][2 * h + 1];
                    float v2 = acc[mt][2 * g + 1][2 * h], v3 = acc[mt][2 * g + 1][2 * h + 1];
                    float mx = fmaxf(fmaxf(v0, v1), fmaxf(v2, v3));
                    mx = fmaxf(mx, __shfl_xor_sync(0xffffffffu, mx, 1));
                    mx = fmaxf(mx, __shfl_xor_sync(0xffffffffu, mx, 2));
                    v0 = expf(v0 - mx); v1 = expf(v1 - mx);
                    v2 = expf(v2 - mx); v3 = expf(v3 - mx);
                    float s = v0 + v1 + v2 + v3;
                    s += __shfl_xor_sync(0xffffffffu, s, 1);
                    s += __shfl_xor_sync(0xffffffffu, s, 2);
                    float inv = 1.0f / s;
                    acc[mt][2 * g][2 * h] = v0 * inv; acc[mt][2 * g][2 * h + 1] = v1 * inv;
                    acc[mt][2 * g + 1][2 * h] = v2 * inv; acc[mt][2 * g + 1][2 * h + 1] = v3 * inv;
                }
    }

    if (effmode == 3) {
        __half* oph = (__half*)out_p;
#pragma unroll
        for (int mt = 0; mt < 2; mt++)
#pragma unroll
            for (int h = 0; h < 2; h++) {
                int row = rowBase + warpm * 32 + mt * 16 + h * 8 + (lane >> 2);
#pragma unroll
                for (int nt = 0; nt < 8; nt++) {
                    int col = colBase + warpn * 64 + nt * 8 + 2 * (lane & 3);
                    *(__half2*)(oph + (size_t)row * CC + col) =
                        __floats2half2_rn(acc[mt][nt][2 * h], acc[mt][nt][2 * h + 1]);
                }
            }
    } else {
#pragma unroll
        for (int mt = 0; mt < 2; mt++)
#pragma unroll
            for (int h = 0; h < 2; h++) {
                int row = rowBase + warpm * 32 + mt * 16 + h * 8 + (lane >> 2);
#pragma unroll
                for (int nt = 0; nt < 8; nt++) {
                    int col = colBase + warpn * 64 + nt * 8 + 2 * (lane & 3);
                    float2 o = {acc[mt][nt][2 * h], acc[mt][nt][2 * h + 1]};
                    *(float2*)(out_p + (size_t)row * Ndim + col) = o;
                }
            }
    }
}

// ---------------- deform: one warp per (n,q,m); fp16 taps, lanes split tap0/tap1 ----------------
__global__ void __launch_bounds__(256) deform_kernel(
    const float* __restrict__ d_loc, const float* __restrict__ d_attn)
{
    int gtid = blockIdx.x * blockDim.x + threadIdx.x;
    int warp = gtid >> 5;
    int lane = gtid & 31;
    if (warp >= NB * LQ * MM) return;

    int m = warp % MM;
    int nq = warp / MM;
    int n = nq / LQ;

    float v = (lane < 16) ? d_loc[(size_t)warp * LP + lane]
                          : d_attn[(size_t)warp * LP + (lane - 16)];

    const int leni[LL] = {2048, 1024, 512, 256};
    const float lenf[LL] = {2048.f, 1024.f, 512.f, 256.f};
    const int starti[LL] = {0, 2048, 3072, 3584};

    const __half2* base2 = (const __half2*)g_value_h + (size_t)n * S_TOTAL * (CC / 2) + m * (DH / 2);
    int tap = lane >> 4;
    int klo = lane & 15;

    float acc0 = 0.f, acc1 = 0.f;
#pragma unroll
    for (int i = 0; i < LP; i++) {
        float loc = __shfl_sync(0xffffffffu, v, i);
        float aw = __shfl_sync(0xffffffffu, v, i + 16);
        int l = i >> 2;
        int Ti = leni[l];
        float pos = loc * lenf[l] - 0.5f;
        float x0f = floorf(pos);
        float frac = pos - x0f;
        int x0 = (int)x0f;
        float w0 = (x0 >= 0 && x0 < Ti) ? (1.0f - frac) : 0.0f;
        float w1 = (x0 + 1 >= 0 && x0 + 1 < Ti) ? frac : 0.0f;
        int t0 = min(max(x0, 0), Ti - 2);
        float wa = (t0 == x0) ? w0 : ((t0 == x0 + 1) ? w1 : 0.0f);
        float wb = (t0 + 1 == x0) ? w0 : ((t0 + 1 == x0 + 1) ? w1 : 0.0f);
        float w = tap ? wb : wa;

        __half2 hv = base2[(size_t)(starti[l] + t0 + tap) * (CC / 2) + klo];
        float2 f = __half22float2(hv);
        float p0 = w * f.x;
        float p1 = w * f.y;
        p0 += __shfl_xor_sync(0xffffffffu, p0, 16);
        p1 += __shfl_xor_sync(0xffffffffu, p1, 16);
        acc0 += aw * p0;
        acc1 += aw * p1;
    }

    if (lane < 16) {
        size_t oi = (size_t)nq * CC + m * DH + 2 * klo;
        __nv_bfloat16 h0 = __float2bfloat16(acc0);
        __nv_bfloat16 h1 = __float2bfloat16(acc1);
        *(__nv_bfloat162*)(g_mx_hi + oi) = __nv_bfloat162(h0, h1);
        *(__nv_bfloat162*)(g_mx_lo + oi) = __nv_bfloat162(
            __float2bfloat16(acc0 - __bfloat162float(h0)),
            __float2bfloat16(acc1 - __bfloat162float(h1)));
    }
}

// ---------------- launch ----------------
extern "C" void kernel_launch(void* const* d_in, const int* in_sizes, int n_in,
                              void* d_out, int out_size)
{
    const float* query  = (const float*)d_in[0];
    const float* rp     = (const float*)d_in[1];
    const float* inp    = (const float*)d_in[2];
    const float* W_off  = (const float*)d_in[5];
    const float* b_off  = (const float*)d_in[6];
    const float* W_attn = (const float*)d_in[7];
    const float* b_attn = (const float*)d_in[8];
    const float* W_val  = (const float*)d_in[9];
    const float* b_val  = (const float*)d_in[10];
    const float* W_out  = (const float*)d_in[11];
    const float* b_out  = (const float*)d_in[12];

    float* out    = (float*)d_out;
    float* o_loc  = out + (size_t)NB * LQ * CC;
    float* o_attn = o_loc + (size_t)NB * LQ * MLP;

    cudaFuncSetAttribute(gemm_hmma_kernel, cudaFuncAttributeMaxDynamicSharedMemorySize, 65536);

    __half* valueh;
    __nv_bfloat16 *ih, *il, *qh, *ql, *mh, *ml;
    __nv_bfloat16 *wvh, *wvl, *woh, *wol, *wah, *wal, *wuh, *wul;
    cudaGetSymbolAddress((void**)&valueh, g_value_h);
    cudaGetSymbolAddress((void**)&ih, g_inp_hi);  cudaGetSymbolAddress((void**)&il, g_inp_lo);
    cudaGetSymbolAddress((void**)&qh, g_q_hi);    cudaGetSymbolAddress((void**)&ql, g_q_lo);
    cudaGetSymbolAddress((void**)&mh, g_mx_hi);   cudaGetSymbolAddress((void**)&ml, g_mx_lo);
    cudaGetSymbolAddress((void**)&wvh, g_wv_hi);  cudaGetSymbolAddress((void**)&wvl, g_wv_lo);
    cudaGetSymbolAddress((void**)&woh, g_wo_hi);  cudaGetSymbolAddress((void**)&wol, g_wo_lo);
    cudaGetSymbolAddress((void**)&wah, g_wa_hi);  cudaGetSymbolAddress((void**)&wal, g_wa_lo);
    cudaGetSymbolAddress((void**)&wuh, g_wu_hi);  cudaGetSymbolAddress((void**)&wul, g_wu_lo);

    // fork/join streams (capturable fork via events)
    cudaStream_t s2;
    cudaStreamCreateWithFlags(&s2, cudaStreamNonBlocking);
    cudaEvent_t e1, e2;
    cudaEventCreateWithFlags(&e1, cudaEventDisableTiming);
    cudaEventCreateWithFlags(&e2, cudaEventDisableTiming);

    prep_weights_kernel<<<(2 * CC * KDIM + 2 * MLP * KDIM + 255) / 256, 256>>>(W_val, W_off, W_attn, W_out);
    split2_kernel<<<((NB * S_TOTAL * CC + NB * LQ * CC) / 4 + 255) / 256, 256>>>(
        inp, ih, il, NB * S_TOTAL * CC / 4, query, qh, ql, NB * LQ * CC / 4);
    cudaEventRecord(e1, 0);
    cudaStreamWaitEvent(s2, e1, 0);

    // side stream: merged loc+attn GEMM (grid.y: 0=loc, 1=attn)
    gemm_hmma_kernel<<<dim3(NB * LQ / 128, 2), 256, 65536, s2>>>(
        qh, ql, woh, wol, b_off, o_loc, MLP, 4, rp, wah, wal, b_attn, o_attn);
    cudaEventRecord(e2, s2);

    // main stream: value GEMM (fp16 natural-layout store)
    gemm_hmma_kernel<<<dim3(NB * S_TOTAL / 128, CC / 128), 256, 65536>>>(
        ih, il, wvh, wvl, b_val, (float*)valueh, CC, 3, nullptr, nullptr, nullptr, nullptr, nullptr);

    // join, then deform + output projection
    cudaStreamWaitEvent(0, e2, 0);
    deform_kernel<<<(NB * LQ * MM * 32) / 256, 256>>>(o_loc, o_attn);
    gemm_hmma_kernel<<<dim3(NB * LQ / 128, CC / 128), 256, 65536>>>(
        mh, ml, wuh, wul, b_out, out, CC, 0, nullptr, nullptr, nullptr, nullptr, nullptr);
}

// round 16
// speedup vs baseline: 1.7222x; 1.1184x over previous
#include <cuda_runtime.h>
#include <cuda_bf16.h>
#include <cuda_fp16.h>
#include <math.h>
#include <stdint.h>

#define NB 8
#define LQ 2048
#define CC 256
#define MM 8
#define LL 4
#define PP 4
#define DH 32
#define S_TOTAL 3840
#define MLP 128
#define LP 16
#define KDIM 256

// ---------------- scratch (no allocs allowed) ----------------
__device__ __align__(16) __half g_value_h[NB * S_TOTAL * CC];   // [n][t][m*32+dh] fp16
__device__ __align__(16) __half g_inp_f16[NB * S_TOTAL * CC];
__device__ __align__(16) __half g_wv_f16[CC * KDIM];
__device__ __align__(16) __nv_bfloat16 g_q_hi[NB * LQ * CC];
__device__ __align__(16) __nv_bfloat16 g_q_lo[NB * LQ * CC];
__device__ __align__(16) __nv_bfloat16 g_mx_hi[NB * LQ * CC];
__device__ __align__(16) __nv_bfloat16 g_mx_lo[NB * LQ * CC];
__device__ __align__(16) __nv_bfloat16 g_wo_hi[MLP * KDIM], g_wo_lo[MLP * KDIM];
__device__ __align__(16) __nv_bfloat16 g_wa_hi[MLP * KDIM], g_wa_lo[MLP * KDIM];
__device__ __align__(16) __nv_bfloat16 g_wu_hi[CC * KDIM], g_wu_lo[CC * KDIM];

// ---------------- helpers ----------------
__device__ __forceinline__ uint32_t smem_u32(const void* p) {
    uint32_t a;
    asm("{ .reg .u64 t; cvta.to.shared.u64 t, %1; cvt.u32.u64 %0, t; }" : "=r"(a) : "l"(p));
    return a;
}
static __device__ __forceinline__ uint32_t swz128(uint32_t off) { return off ^ ((off >> 3) & 0x70); }
static __device__ __forceinline__ uint32_t swz64(uint32_t off) { return off ^ ((off >> 3) & 0x30); }

#define CP_ASYNC16(dst, src) \
    asm volatile("cp.async.cg.shared.global [%0], [%1], 16;" :: "r"(dst), "l"(src))
#define CP_COMMIT() asm volatile("cp.async.commit_group;" ::: "memory")
#define CP_WAIT1() asm volatile("cp.async.wait_group 1;" ::: "memory")
#define CP_WAIT0() asm volatile("cp.async.wait_group 0;" ::: "memory")

#define LDMATRIX_X4(r0, r1, r2, r3, addr) \
    asm volatile("ldmatrix.sync.aligned.m8n8.x4.shared.b16 {%0,%1,%2,%3}, [%4];" \
        : "=r"(r0), "=r"(r1), "=r"(r2), "=r"(r3) : "r"(addr))

#define MMA_BF16_2(c, a, b0v, b1v) \
    asm volatile("mma.sync.aligned.m16n8k16.row.col.f32.bf16.bf16.f32 " \
        "{%0,%1,%2,%3}, {%4,%5,%6,%7}, {%8,%9}, {%0,%1,%2,%3};" \
        : "+f"((c)[0]), "+f"((c)[1]), "+f"((c)[2]), "+f"((c)[3]) \
        : "r"((a)[0]), "r"((a)[1]), "r"((a)[2]), "r"((a)[3]), "r"(b0v), "r"(b1v))

#define MMA_FP16_2(c, a, b0v, b1v) \
    asm volatile("mma.sync.aligned.m16n8k16.row.col.f32.f16.f16.f32 " \
        "{%0,%1,%2,%3}, {%4,%5,%6,%7}, {%8,%9}, {%0,%1,%2,%3};" \
        : "+f"((c)[0]), "+f"((c)[1]), "+f"((c)[2]), "+f"((c)[3]) \
        : "r"((a)[0]), "r"((a)[1]), "r"((a)[2]), "r"((a)[3]), "r"(b0v), "r"(b1v))

// ---------------- weight transpose + split ----------------
// Wv -> fp16 transposed; Wo/Wa/Wu -> bf16 hi/lo transposed
__global__ void prep_weights_kernel(
    const float* __restrict__ Wv, const float* __restrict__ Wo,
    const float* __restrict__ Wa, const float* __restrict__ Wu)
{
    int i = blockIdx.x * blockDim.x + threadIdx.x;
    if (i < CC * KDIM) {
        int k = i & (KDIM - 1), n = i >> 8;
        g_wv_f16[i] = __float2half(Wv[k * CC + n]);
        return;
    }
    i -= CC * KDIM;
    const float* W; __nv_bfloat16 *H, *Lo; int Nw, j;
    if (i < MLP * KDIM)          { W = Wo; H = g_wo_hi; Lo = g_wo_lo; Nw = MLP; j = i; }
    else if (i < 2 * MLP * KDIM) { W = Wa; H = g_wa_hi; Lo = g_wa_lo; Nw = MLP; j = i - MLP * KDIM; }
    else if (i < 2 * MLP * KDIM + CC * KDIM) { W = Wu; H = g_wu_hi; Lo = g_wu_lo; Nw = CC; j = i - 2 * MLP * KDIM; }
    else return;
    int k = j & (KDIM - 1);
    int n = j >> 8;
    float x = W[k * Nw + n];
    __nv_bfloat16 h = __float2bfloat16(x);
    H[j] = h;
    Lo[j] = __float2bfloat16(x - __bfloat162float(h));
}

// ---------------- fused activation convert: inp->fp16, query->bf16 hi/lo ----------------
__global__ void __launch_bounds__(256) split2_kernel(
    const float* __restrict__ xa, __half* __restrict__ f16a, int n4a,
    const float* __restrict__ xb, __nv_bfloat16* __restrict__ hib, __nv_bfloat16* __restrict__ lob, int n4b)
{
    int i = blockIdx.x * blockDim.x + threadIdx.x;
    if (i < n4a) {
        float4 v = ((const float4*)xa)[i];
        ((__half2*)f16a)[2 * i]     = __floats2half2_rn(v.x, v.y);
        ((__half2*)f16a)[2 * i + 1] = __floats2half2_rn(v.z, v.w);
        return;
    }
    i -= n4a;
    if (i >= n4b) return;
    float4 v = ((const float4*)xb)[i];
    float f[4] = {v.x, v.y, v.z, v.w};
    __nv_bfloat16 h[4], l[4];
#pragma unroll
    for (int t = 0; t < 4; t++) {
        h[t] = __float2bfloat16(f[t]);
        l[t] = __float2bfloat16(f[t] - __bfloat162float(h[t]));
    }
    ((__nv_bfloat162*)hib)[2 * i]     = __nv_bfloat162(h[0], h[1]);
    ((__nv_bfloat162*)hib)[2 * i + 1] = __nv_bfloat162(h[2], h[3]);
    ((__nv_bfloat162*)lob)[2 * i]     = __nv_bfloat162(l[0], l[1]);
    ((__nv_bfloat162*)lob)[2 * i + 1] = __nv_bfloat162(l[2], l[3]);
}

// ---------------- single-pass fp16 GEMM (value projection): fp16 out [n][t][c] ----------------
// BM=128 BN=128 BK=64, 2-stage x 32KB = 64KB smem, 2 CTA/SM.
__global__ void __launch_bounds__(256, 2) gemm_fp16_kernel(
    const __half* __restrict__ A, const __half* __restrict__ Bt,
    const float* __restrict__ bias, __half* __restrict__ out)
{
    extern __shared__ char smem[];
    uint32_t sb = smem_u32(smem);
    const int tid = threadIdx.x;
    const int lane = tid & 31;
    const int wid = tid >> 5;
    const int warpm = wid & 3;
    const int warpn = wid >> 2;
    const int rowBase = blockIdx.x * 128;
    const int colBase = blockIdx.y * 128;

    const int seg = tid & 7;
    const int r0 = tid >> 3;

    float acc[2][8][4];
#pragma unroll
    for (int a = 0; a < 2; a++)
#pragma unroll
        for (int b = 0; b < 8; b++)
#pragma unroll
            for (int c = 0; c < 4; c++) acc[a][b][c] = 0.f;

#define LOAD_SLAB16(c, stage) do { \
        uint32_t _base = sb + (stage) * 32768u; \
        _Pragma("unroll") \
        for (int _j = 0; _j < 4; _j++) { \
            int _row = r0 + 32 * _j; \
            uint32_t _sw = swz128(_row * 128 + seg * 16); \
            CP_ASYNC16(_base + _sw,          A  + (size_t)(rowBase + _row) * KDIM + (c) * 64 + seg * 8); \
            CP_ASYNC16(_base + 16384u + _sw, Bt + (size_t)(colBase + _row) * KDIM + (c) * 64 + seg * 8); \
        } \
        CP_COMMIT(); \
    } while (0)

    LOAD_SLAB16(0, 0);

    for (int c = 0; c < 4; c++) {
        int stage = c & 1;
        if (c < 3) { LOAD_SLAB16(c + 1, stage ^ 1); CP_WAIT1(); }
        else CP_WAIT0();
        __syncthreads();

        uint32_t base = sb + stage * 32768u;
#pragma unroll
        for (int kk = 0; kk < 4; kk++) {
            uint32_t af[2][4];
#pragma unroll
            for (int mt = 0; mt < 2; mt++) {
                uint32_t aoff = swz128((warpm * 32 + mt * 16 + (lane & 15)) * 128
                                       + kk * 32 + ((lane >> 4) << 4));
                LDMATRIX_X4(af[mt][0], af[mt][1], af[mt][2], af[mt][3], base + aoff);
            }
#pragma unroll
            for (int pb = 0; pb < 4; pb++) {
                uint32_t boff = swz128((warpn * 64 + pb * 16 + ((lane >> 4) << 3) + (lane & 7)) * 128
                                       + kk * 32 + (((lane >> 3) & 1) << 4));
                uint32_t b0, b1, b2, b3;
                LDMATRIX_X4(b0, b1, b2, b3, base + 16384u + boff);
#pragma unroll
                for (int mt = 0; mt < 2; mt++) {
                    MMA_FP16_2(acc[mt][2 * pb],     af[mt], b0, b1);
                    MMA_FP16_2(acc[mt][2 * pb + 1], af[mt], b2, b3);
                }
            }
        }
        __syncthreads();
    }

    // epilogue: bias + fp16 store, natural layout
#pragma unroll
    for (int mt = 0; mt < 2; mt++)
#pragma unroll
        for (int h = 0; h < 2; h++) {
            int row = rowBase + warpm * 32 + mt * 16 + h * 8 + (lane >> 2);
#pragma unroll
            for (int nt = 0; nt < 8; nt++) {
                int col = colBase + warpn * 64 + nt * 8 + 2 * (lane & 3);
                float b0 = __ldg(&bias[col]);
                float b1 = __ldg(&bias[col + 1]);
                *(__half2*)(out + (size_t)row * CC + col) =
                    __floats2half2_rn(acc[mt][nt][2 * h] + b0, acc[mt][nt][2 * h + 1] + b1);
            }
        }
}

// ---------------- HMMA GEMM, shared-tile 3-pass, BK=32, 2 CTA/SM ----------------
// modes: 0 = bias->f32; 4 = paired side (y0: loc, y1: attn)
__global__ void __launch_bounds__(256, 2) gemm_hmma_kernel(
    const __nv_bfloat16* __restrict__ Ahi, const __nv_bfloat16* __restrict__ Alo,
    const __nv_bfloat16* __restrict__ Bhi, const __nv_bfloat16* __restrict__ Blo,
    const float* __restrict__ bias, float* __restrict__ out,
    int Ndim, int mode, const float* __restrict__ rp,
    const __nv_bfloat16* __restrict__ B2h, const __nv_bfloat16* __restrict__ B2l,
    const float* __restrict__ bias2, float* __restrict__ out2)
{
    extern __shared__ char smem[];
    uint32_t sb = smem_u32(smem);
    const int tid = threadIdx.x;
    const int lane = tid & 31;
    const int wid = tid >> 5;
    const int warpm = wid & 3;
    const int warpn = wid >> 2;
    const int rowBase = blockIdx.x * 128;
    int colBase = blockIdx.y * 128;

    const __nv_bfloat16 *Bh_p = Bhi, *Bl_p = Blo;
    const float* bias_p = bias;
    float* out_p = out;
    int effmode = mode;
    if (mode == 4) {
        colBase = 0;
        if (blockIdx.y == 0) { effmode = 1; }
        else { effmode = 2; Bh_p = B2h; Bl_p = B2l; bias_p = bias2; out_p = out2; }
    }

    const int seg = tid & 3;
    const int r0 = tid >> 2;

    float acc[2][8][4];
#pragma unroll
    for (int a = 0; a < 2; a++)
#pragma unroll
        for (int b = 0; b < 8; b++)
#pragma unroll
            for (int c = 0; c < 4; c++) acc[a][b][c] = 0.f;

#define LOAD_SLAB(c, stage) do { \
        uint32_t _base = sb + (stage) * 32768u; \
        _Pragma("unroll") \
        for (int _j = 0; _j < 2; _j++) { \
            int _row = r0 + 64 * _j; \
            uint32_t _sw = swz64(_row * 64 + seg * 16); \
            size_t _ga = (size_t)(rowBase + _row) * KDIM + (c) * 32 + seg * 8; \
            size_t _gb = (size_t)(colBase + _row) * KDIM + (c) * 32 + seg * 8; \
            CP_ASYNC16(_base + _sw,          Ahi  + _ga); \
            CP_ASYNC16(_base + 8192u  + _sw, Alo  + _ga); \
            CP_ASYNC16(_base + 16384u + _sw, Bh_p + _gb); \
            CP_ASYNC16(_base + 24576u + _sw, Bl_p + _gb); \
        } \
        CP_COMMIT(); \
    } while (0)

    LOAD_SLAB(0, 0);

    for (int c = 0; c < 8; c++) {
        int stage = c & 1;
        if (c < 7) { LOAD_SLAB(c + 1, stage ^ 1); CP_WAIT1(); }
        else CP_WAIT0();
        __syncthreads();

        uint32_t base = sb + stage * 32768u;
#pragma unroll
        for (int kk = 0; kk < 2; kk++) {
            uint32_t ah[2][4], al[2][4];
#pragma unroll
            for (int mt = 0; mt < 2; mt++) {
                uint32_t aoff = swz64((warpm * 32 + mt * 16 + (lane & 15)) * 64
                                      + kk * 32 + ((lane >> 4) << 4));
                LDMATRIX_X4(ah[mt][0], ah[mt][1], ah[mt][2], ah[mt][3], base + aoff);
                LDMATRIX_X4(al[mt][0], al[mt][1], al[mt][2], al[mt][3], base + 8192u + aoff);
            }
#pragma unroll
            for (int pb = 0; pb < 4; pb++) {
                uint32_t boff = swz64((warpn * 64 + pb * 16 + ((lane >> 4) << 3) + (lane & 7)) * 64
                                      + kk * 32 + (((lane >> 3) & 1) << 4));
                uint32_t h0, h1, h2, h3, l0, l1, l2, l3;
                LDMATRIX_X4(h0, h1, h2, h3, base + 16384u + boff);
                LDMATRIX_X4(l0, l1, l2, l3, base + 24576u + boff);
#pragma unroll
                for (int mt = 0; mt < 2; mt++) {
                    MMA_BF16_2(acc[mt][2 * pb],     ah[mt], h0, h1);
                    MMA_BF16_2(acc[mt][2 * pb + 1], ah[mt], h2, h3);
                    MMA_BF16_2(acc[mt][2 * pb],     ah[mt], l0, l1);
                    MMA_BF16_2(acc[mt][2 * pb + 1], ah[mt], l2, l3);
                    MMA_BF16_2(acc[mt][2 * pb],     al[mt], h0, h1);
                    MMA_BF16_2(acc[mt][2 * pb + 1], al[mt], h2, h3);
                }
            }
        }
        __syncthreads();
    }

    // ---- epilogue ----
#pragma unroll
    for (int nt = 0; nt < 8; nt++) {
        int c = colBase + warpn * 64 + nt * 8 + 2 * (lane & 3);
        float b0 = __ldg(&bias_p[c]);
        float b1 = __ldg(&bias_p[c + 1]);
#pragma unroll
        for (int mt = 0; mt < 2; mt++) {
            acc[mt][nt][0] += b0; acc[mt][nt][1] += b1;
            acc[mt][nt][2] += b0; acc[mt][nt][3] += b1;
        }
    }

    if (effmode == 1) {
#pragma unroll
        for (int mt = 0; mt < 2; mt++)
#pragma unroll
            for (int h = 0; h < 2; h++) {
                int row = rowBase + warpm * 32 + mt * 16 + h * 8 + (lane >> 2);
                float4 rp4 = __ldg((const float4*)rp + row);
                float rparr[4] = {rp4.x, rp4.y, rp4.z, rp4.w};
#pragma unroll
                for (int nt = 0; nt < 8; nt++) {
                    int l = (((colBase + warpn * 64 + nt * 8 + 2 * (lane & 3))) >> 2) & 3;
                    float invlen = __uint_as_float((uint32_t)(116 + l) << 23);
                    acc[mt][nt][2 * h]     = rparr[l] + acc[mt][nt][2 * h] * invlen;
                    acc[mt][nt][2 * h + 1] = rparr[l] + acc[mt][nt][2 * h + 1] * invlen;
                }
            }
    } else if (effmode == 2) {
#pragma unroll
        for (int mt = 0; mt < 2; mt++)
#pragma unroll
            for (int h = 0; h < 2; h++)
#pragma unroll
                for (int g = 0; g < 4; g++) {
                    float v0 = acc[mt][2 * g][2 * h], v1 = acc[mt][2 * g][2 * h + 1];
                    float v2 = acc[mt][2 * g + 1][2 * h], v3 = acc[mt][2 * g + 1][2 * h + 1];
                    float mx = fmaxf(fmaxf(v0, v1), fmaxf(v2, v3));
                    mx = fmaxf(mx, __shfl_xor_sync(0xffffffffu, mx, 1));
                    mx = fmaxf(mx, __shfl_xor_sync(0xffffffffu, mx, 2));
                    v0 = expf(v0 - mx); v1 = expf(v1 - mx);
                    v2 = expf(v2 - mx); v3 = expf(v3 - mx);
                    float s = v0 + v1 + v2 + v3;
                    s += __shfl_xor_sync(0xffffffffu, s, 1);
                    s += __shfl_xor_sync(0xffffffffu, s, 2);
                    float inv = 1.0f / s;
                    acc[mt][2 * g][2 * h] = v0 * inv; acc[mt][2 * g][2 * h + 1] = v1 * inv;
                    acc[mt][2 * g + 1][2 * h] = v2 * inv; acc[mt][2 * g + 1][2 * h + 1] = v3 * inv;
                }
    }

#pragma unroll
    for (int mt = 0; mt < 2; mt++)
#pragma unroll
        for (int h = 0; h < 2; h++) {
            int row = rowBase + warpm * 32 + mt * 16 + h * 8 + (lane >> 2);
#pragma unroll
            for (int nt = 0; nt < 8; nt++) {
                int col = colBase + warpn * 64 + nt * 8 + 2 * (lane & 3);
                float2 o = {acc[mt][nt][2 * h], acc[mt][nt][2 * h + 1]};
                *(float2*)(out_p + (size_t)row * Ndim + col) = o;
            }
        }
}

// ---------------- deform: one warp per (n,q,m); fp16 taps, lanes split tap0/tap1 ----------------
__global__ void __launch_bounds__(256) deform_kernel(
    const float* __restrict__ d_loc, const float* __restrict__ d_attn)
{
    int gtid = blockIdx.x * blockDim.x + threadIdx.x;
    int warp = gtid >> 5;
    int lane = gtid & 31;
    if (warp >= NB * LQ * MM) return;

    int m = warp % MM;
    int nq = warp / MM;
    int n = nq / LQ;

    float v = (lane < 16) ? d_loc[(size_t)warp * LP + lane]
                          : d_attn[(size_t)warp * LP + (lane - 16)];

    const int leni[LL] = {2048, 1024, 512, 256};
    const float lenf[LL] = {2048.f, 1024.f, 512.f, 256.f};
    const int starti[LL] = {0, 2048, 3072, 3584};

    const __half2* base2 = (const __half2*)g_value_h + (size_t)n * S_TOTAL * (CC / 2) + m * (DH / 2);
    int tap = lane >> 4;
    int klo = lane & 15;

    float acc0 = 0.f, acc1 = 0.f;
#pragma unroll
    for (int i = 0; i < LP; i++) {
        float loc = __shfl_sync(0xffffffffu, v, i);
        float aw = __shfl_sync(0xffffffffu, v, i + 16);
        int l = i >> 2;
        int Ti = leni[l];
        float pos = loc * lenf[l] - 0.5f;
        float x0f = floorf(pos);
        float frac = pos - x0f;
        int x0 = (int)x0f;
        float w0 = (x0 >= 0 && x0 < Ti) ? (1.0f - frac) : 0.0f;
        float w1 = (x0 + 1 >= 0 && x0 + 1 < Ti) ? frac : 0.0f;
        int t0 = min(max(x0, 0), Ti - 2);
        float wa = (t0 == x0) ? w0 : ((t0 == x0 + 1) ? w1 : 0.0f);
        float wb = (t0 + 1 == x0) ? w0 : ((t0 + 1 == x0 + 1) ? w1 : 0.0f);
        float w = tap ? wb : wa;

        __half2 hv = base2[(size_t)(starti[l] + t0 + tap) * (CC / 2) + klo];
        float2 f = __half22float2(hv);
        float p0 = w * f.x;
        float p1 = w * f.y;
        p0 += __shfl_xor_sync(0xffffffffu, p0, 16);
        p1 += __shfl_xor_sync(0xffffffffu, p1, 16);
        acc0 += aw * p0;
        acc1 += aw * p1;
    }

    if (lane < 16) {
        size_t oi = (size_t)nq * CC + m * DH + 2 * klo;
        __nv_bfloat16 h0 = __float2bfloat16(acc0);
        __nv_bfloat16 h1 = __float2bfloat16(acc1);
        *(__nv_bfloat162*)(g_mx_hi + oi) = __nv_bfloat162(h0, h1);
        *(__nv_bfloat162*)(g_mx_lo + oi) = __nv_bfloat162(
            __float2bfloat16(acc0 - __bfloat162float(h0)),
            __float2bfloat16(acc1 - __bfloat162float(h1)));
    }
}

// ---------------- launch ----------------
extern "C" void kernel_launch(void* const* d_in, const int* in_sizes, int n_in,
                              void* d_out, int out_size)
{
    const float* query  = (const float*)d_in[0];
    const float* rp     = (const float*)d_in[1];
    const float* inp    = (const float*)d_in[2];
    const float* W_off  = (const float*)d_in[5];
    const float* b_off  = (const float*)d_in[6];
    const float* W_attn = (const float*)d_in[7];
    const float* b_attn = (const float*)d_in[8];
    const float* W_val  = (const float*)d_in[9];
    const float* b_val  = (const float*)d_in[10];
    const float* W_out  = (const float*)d_in[11];
    const float* b_out  = (const float*)d_in[12];

    float* out    = (float*)d_out;
    float* o_loc  = out + (size_t)NB * LQ * CC;
    float* o_attn = o_loc + (size_t)NB * LQ * MLP;

    cudaFuncSetAttribute(gemm_hmma_kernel, cudaFuncAttributeMaxDynamicSharedMemorySize, 65536);
    cudaFuncSetAttribute(gemm_fp16_kernel, cudaFuncAttributeMaxDynamicSharedMemorySize, 65536);

    __half *valueh, *if16, *wvf;
    __nv_bfloat16 *qh, *ql, *mh, *ml;
    __nv_bfloat16 *woh, *wol, *wah, *wal, *wuh, *wul;
    cudaGetSymbolAddress((void**)&valueh, g_value_h);
    cudaGetSymbolAddress((void**)&if16, g_inp_f16);
    cudaGetSymbolAddress((void**)&wvf, g_wv_f16);
    cudaGetSymbolAddress((void**)&qh, g_q_hi);    cudaGetSymbolAddress((void**)&ql, g_q_lo);
    cudaGetSymbolAddress((void**)&mh, g_mx_hi);   cudaGetSymbolAddress((void**)&ml, g_mx_lo);
    cudaGetSymbolAddress((void**)&woh, g_wo_hi);  cudaGetSymbolAddress((void**)&wol, g_wo_lo);
    cudaGetSymbolAddress((void**)&wah, g_wa_hi);  cudaGetSymbolAddress((void**)&wal, g_wa_lo);
    cudaGetSymbolAddress((void**)&wuh, g_wu_hi);  cudaGetSymbolAddress((void**)&wul, g_wu_lo);

    // fork/join streams (capturable fork via events)
    cudaStream_t s2;
    cudaStreamCreateWithFlags(&s2, cudaStreamNonBlocking);
    cudaEvent_t e1, e2;
    cudaEventCreateWithFlags(&e1, cudaEventDisableTiming);
    cudaEventCreateWithFlags(&e2, cudaEventDisableTiming);

    prep_weights_kernel<<<(2 * CC * KDIM + 2 * MLP * KDIM + 255) / 256, 256>>>(W_val, W_off, W_attn, W_out);
    split2_kernel<<<((NB * S_TOTAL * CC + NB * LQ * CC) / 4 + 255) / 256, 256>>>(
        inp, if16, NB * S_TOTAL * CC / 4, query, qh, ql, NB * LQ * CC / 4);
    cudaEventRecord(e1, 0);
    cudaStreamWaitEvent(s2, e1, 0);

    // side stream: merged loc+attn GEMM (grid.y: 0=loc, 1=attn)
    gemm_hmma_kernel<<<dim3(NB * LQ / 128, 2), 256, 65536, s2>>>(
        qh, ql, woh, wol, b_off, o_loc, MLP, 4, rp, wah, wal, b_attn, o_attn);
    cudaEventRecord(e2, s2);

    // main stream: value GEMM, single-pass fp16
    gemm_fp16_kernel<<<dim3(NB * S_TOTAL / 128, CC / 128), 256, 65536>>>(if16, wvf, b_val, valueh);

    // join, then deform + output projection
    cudaStreamWaitEvent(0, e2, 0);
    deform_kernel<<<(NB * LQ * MM * 32) / 256, 256>>>(o_loc, o_attn);
    gemm_hmma_kernel<<<dim3(NB * LQ / 128, CC / 128), 256, 65536>>>(
        mh, ml, wuh, wul, b_out, out, CC, 0, nullptr, nullptr, nullptr, nullptr, nullptr);
}